// round 1
// baseline (speedup 1.0000x reference)
#include <cuda_runtime.h>
#include <math.h>

#define B_    4
#define S_    1024
#define DIM_  2048
#define H_    16
#define HD_   128
#define BSTOT 4096   // B_*S_

// ---------------- scratch (no runtime allocation allowed) ----------------
__device__ float d_Q[(size_t)H_*B_*S_*HD_];   // (H,B,S,HD)
__device__ float d_K[(size_t)H_*B_*S_*HD_];
__device__ float d_V[(size_t)H_*B_*S_*HD_];
__device__ float d_A[(size_t)H_*S_*S_];       // (H,S,S)
__device__ float d_O[(size_t)BSTOT*DIM_];     // (B*S, DIM)
__device__ float d_G[(size_t)BSTOT*DIM_];     // gate buffer W, then W*Y
__device__ float d_rs[H_*S_];                 // 1/sqrt(rowsum_t)
__device__ float d_l2g[H_];                   // log2(gamma_h)

// ---------------- decay tables ----------------
// rowsum(t) = sum_{m=0}^{t} gamma^{-m} = (r^{t+1}-1)/(r-1), r = 1/gamma > 1
__global__ void decay_kernel() {
    int h = blockIdx.x;
    int j = threadIdx.x;
    double g  = 1.0 - exp2((double)(-5 - h));
    double r  = 1.0 / g;
    double rp = pow(r, (double)(j + 1));
    double Sj = (rp - 1.0) / (r - 1.0);
    d_rs[h * S_ + j] = (float)(1.0 / sqrt(Sj));
    if (j == 0) d_l2g[h] = (float)log2(g);
}

// ---------------- QKV projection ----------------
// dst[(h*B+b)*S*HD + s*HD + e] = sum_d src[b,s,h*HD+d] * Wh[h,d,e]
// 64x128 tile, K=128 in chunks of 32. blockIdx: (row_tile, head, which)
__global__ void qkv_kernel(const float* __restrict__ x,
                           const float* __restrict__ kin,
                           const float* __restrict__ vin,
                           const float* __restrict__ Wh) {
    const int h     = blockIdx.y;
    const int which = blockIdx.z;
    const float* src = (which == 0) ? x : (which == 1) ? kin : vin;
    float* dst = (which == 0) ? d_Q : (which == 1) ? d_K : d_V;
    const int m0 = blockIdx.x * 64;

    __shared__ float Xs[32][65];
    __shared__ float Ws[32][128];

    const int tid = threadIdx.x;
    const int tx = tid & 15, ty = tid >> 4;
    float acc[4][8];
#pragma unroll
    for (int i = 0; i < 4; i++)
#pragma unroll
        for (int j = 0; j < 8; j++) acc[i][j] = 0.0f;

    for (int k0 = 0; k0 < HD_; k0 += 32) {
        // X tile: 64 rows x 32 cols (transposed into Xs)
#pragma unroll
        for (int i = 0; i < 2; i++) {
            int idx = tid + i * 256;          // 0..511
            int r = idx >> 3, c4 = idx & 7;
            int row = m0 + r;
            int b = row >> 10, s = row & 1023;
            float4 vv = *(const float4*)&src[(size_t)(b * S_ + s) * DIM_ + h * HD_ + k0 + c4 * 4];
            Xs[c4 * 4 + 0][r] = vv.x;
            Xs[c4 * 4 + 1][r] = vv.y;
            Xs[c4 * 4 + 2][r] = vv.z;
            Xs[c4 * 4 + 3][r] = vv.w;
        }
        // W tile: 32 rows x 128 cols (direct)
#pragma unroll
        for (int i = 0; i < 4; i++) {
            int idx = tid + i * 256;          // 0..1023
            int r = idx >> 5, c4 = idx & 31;
            *(float4*)&Ws[r][c4 * 4] =
                *(const float4*)&Wh[((size_t)h * HD_ + k0 + r) * HD_ + c4 * 4];
        }
        __syncthreads();
#pragma unroll
        for (int kk = 0; kk < 32; kk++) {
            float a[4];
#pragma unroll
            for (int i = 0; i < 4; i++) a[i] = Xs[kk][ty * 4 + i];
            float4 b0 = *(float4*)&Ws[kk][tx * 8];
            float4 b1 = *(float4*)&Ws[kk][tx * 8 + 4];
            float bb[8] = {b0.x, b0.y, b0.z, b0.w, b1.x, b1.y, b1.z, b1.w};
#pragma unroll
            for (int i = 0; i < 4; i++)
#pragma unroll
                for (int j = 0; j < 8; j++) acc[i][j] += a[i] * bb[j];
        }
        __syncthreads();
    }
#pragma unroll
    for (int i = 0; i < 4; i++) {
        int row = m0 + ty * 4 + i;
        int b = row >> 10, s = row & 1023;
        float* drow = dst + ((size_t)(h * B_ + b) * S_ + s) * HD_ + tx * 8;
        float4 o0 = {acc[i][0], acc[i][1], acc[i][2], acc[i][3]};
        float4 o1 = {acc[i][4], acc[i][5], acc[i][6], acc[i][7]};
        *(float4*)&drow[0] = o0;
        *(float4*)&drow[4] = o1;
    }
}

// ---------------- scores + mask + batch-sum fused as GEMM ----------------
// A[h,s,t] = (t>s) ? 1 : max(|SB * inv_sqrt_hd * gamma^(t-s) * rs[t]|, 1)
// SB[h,s,t] = sum over (b,e) of Q[h,b,s,e]*K[h,b,t,e]  (K-dim = 512)
__global__ void scores_kernel() {
    const int h  = blockIdx.z;
    const int t0 = blockIdx.x * 128;
    const int s0 = blockIdx.y * 64;

    __shared__ float Qs[32][65];
    __shared__ float Ks[32][132];

    const int tid = threadIdx.x;
    const int tx = tid & 15, ty = tid >> 4;
    float acc[4][8];
#pragma unroll
    for (int i = 0; i < 4; i++)
#pragma unroll
        for (int j = 0; j < 8; j++) acc[i][j] = 0.0f;

    const float* Qh = d_Q + (size_t)h * B_ * S_ * HD_;
    const float* Kh = d_K + (size_t)h * B_ * S_ * HD_;

    for (int kk0 = 0; kk0 < B_ * HD_; kk0 += 32) {
        int b = kk0 >> 7, e0 = kk0 & 127;
        const float* Qb = Qh + (size_t)b * S_ * HD_;
        const float* Kb = Kh + (size_t)b * S_ * HD_;
        // Q tile 64 x 32 (transposed)
#pragma unroll
        for (int i = 0; i < 2; i++) {
            int idx = tid + i * 256;
            int r = idx >> 3, c4 = idx & 7;
            float4 vv = *(const float4*)&Qb[(size_t)(s0 + r) * HD_ + e0 + c4 * 4];
            Qs[c4 * 4 + 0][r] = vv.x;
            Qs[c4 * 4 + 1][r] = vv.y;
            Qs[c4 * 4 + 2][r] = vv.z;
            Qs[c4 * 4 + 3][r] = vv.w;
        }
        // K tile 128 x 32 (transposed)
#pragma unroll
        for (int i = 0; i < 4; i++) {
            int idx = tid + i * 256;          // 0..1023
            int r = idx >> 3, c4 = idx & 7;
            float4 vv = *(const float4*)&Kb[(size_t)(t0 + r) * HD_ + e0 + c4 * 4];
            Ks[c4 * 4 + 0][r] = vv.x;
            Ks[c4 * 4 + 1][r] = vv.y;
            Ks[c4 * 4 + 2][r] = vv.z;
            Ks[c4 * 4 + 3][r] = vv.w;
        }
        __syncthreads();
#pragma unroll
        for (int kk = 0; kk < 32; kk++) {
            float a[4];
#pragma unroll
            for (int i = 0; i < 4; i++) a[i] = Qs[kk][ty * 4 + i];
            float4 b0 = *(float4*)&Ks[kk][tx * 8];
            float4 b1 = *(float4*)&Ks[kk][tx * 8 + 4];
            float bb[8] = {b0.x, b0.y, b0.z, b0.w, b1.x, b1.y, b1.z, b1.w};
#pragma unroll
            for (int i = 0; i < 4; i++)
#pragma unroll
                for (int j = 0; j < 8; j++) acc[i][j] += a[i] * bb[j];
        }
        __syncthreads();
    }

    const float l2g = d_l2g[h];
    const float inv_sqrt_hd = 0.08838834764831845f;  // 1/sqrt(128)
    float* Ah = d_A + (size_t)h * S_ * S_;
#pragma unroll
    for (int i = 0; i < 4; i++) {
        int s = s0 + ty * 4 + i;
#pragma unroll
        for (int j = 0; j < 8; j++) {
            int t = t0 + tx * 8 + j;
            float val;
            if (t > s) {
                val = 1.0f;
            } else {
                float dn = exp2f((float)(t - s) * l2g) * d_rs[h * S_ + t];
                val = fmaxf(fabsf(acc[i][j] * inv_sqrt_hd * dn), 1.0f);
            }
            Ah[(size_t)s * S_ + t] = val;
        }
    }
}

// ---------------- O = A @ V per (b,h) ----------------
// O[(b*S+s)*DIM + h*HD + e] = sum_t A[h,s,t] * V[h,b,t,e]
__global__ void ogemm_kernel() {
    const int bh = blockIdx.y;        // b*H + h
    const int b = bh >> 4, h = bh & 15;
    const int s0 = blockIdx.x * 64;

    __shared__ float As[32][65];
    __shared__ float Vs[32][128];

    const int tid = threadIdx.x;
    const int tx = tid & 15, ty = tid >> 4;
    float acc[4][8];
#pragma unroll
    for (int i = 0; i < 4; i++)
#pragma unroll
        for (int j = 0; j < 8; j++) acc[i][j] = 0.0f;

    const float* Ah = d_A + (size_t)h * S_ * S_;
    const float* Vb = d_V + ((size_t)h * B_ + b) * S_ * HD_;

    for (int t0 = 0; t0 < S_; t0 += 32) {
        // A tile 64 x 32 (transposed)
#pragma unroll
        for (int i = 0; i < 2; i++) {
            int idx = tid + i * 256;
            int r = idx >> 3, c4 = idx & 7;
            float4 vv = *(const float4*)&Ah[(size_t)(s0 + r) * S_ + t0 + c4 * 4];
            As[c4 * 4 + 0][r] = vv.x;
            As[c4 * 4 + 1][r] = vv.y;
            As[c4 * 4 + 2][r] = vv.z;
            As[c4 * 4 + 3][r] = vv.w;
        }
        // V tile 32 x 128 (direct)
#pragma unroll
        for (int i = 0; i < 4; i++) {
            int idx = tid + i * 256;
            int r = idx >> 5, c4 = idx & 31;
            *(float4*)&Vs[r][c4 * 4] =
                *(const float4*)&Vb[(size_t)(t0 + r) * HD_ + c4 * 4];
        }
        __syncthreads();
#pragma unroll
        for (int kk = 0; kk < 32; kk++) {
            float a[4];
#pragma unroll
            for (int i = 0; i < 4; i++) a[i] = As[kk][ty * 4 + i];
            float4 b0 = *(float4*)&Vs[kk][tx * 8];
            float4 b1 = *(float4*)&Vs[kk][tx * 8 + 4];
            float bb[8] = {b0.x, b0.y, b0.z, b0.w, b1.x, b1.y, b1.z, b1.w};
#pragma unroll
            for (int i = 0; i < 4; i++)
#pragma unroll
                for (int j = 0; j < 8; j++) acc[i][j] += a[i] * bb[j];
        }
        __syncthreads();
    }
#pragma unroll
    for (int i = 0; i < 4; i++) {
        int s = s0 + ty * 4 + i;
        float* orow = d_O + (size_t)(b * S_ + s) * DIM_ + h * HD_ + tx * 8;
        float4 o0 = {acc[i][0], acc[i][1], acc[i][2], acc[i][3]};
        float4 o1 = {acc[i][4], acc[i][5], acc[i][6], acc[i][7]};
        *(float4*)&orow[0] = o0;
        *(float4*)&orow[4] = o1;
    }
}

// ---------------- big FF GEMM: C(4096x2048) = A(4096x2048) @ B(2048x2048) ----
// mode 0: C = relu(Aparam @ B) -> d_G       (gate branch)
// mode 1: C = d_G @ B          -> Cparam    (output projection)
__global__ void ff_kernel(const float* __restrict__ Aparam,
                          const float* __restrict__ Bm,
                          float* __restrict__ Cparam, int mode) {
    const float* Am = (mode == 0) ? Aparam : d_G;
    float* Cm       = (mode == 0) ? d_G : Cparam;

    const int n0 = blockIdx.x * 128;
    const int m0 = blockIdx.y * 128;

    __shared__ float As[16][132];
    __shared__ float Bs[16][128];

    const int tid = threadIdx.x;
    const int tx = tid & 15, ty = tid >> 4;
    float acc[8][8];
#pragma unroll
    for (int i = 0; i < 8; i++)
#pragma unroll
        for (int j = 0; j < 8; j++) acc[i][j] = 0.0f;

    for (int k0 = 0; k0 < DIM_; k0 += 16) {
        // A tile: 128 x 16 (transposed)
#pragma unroll
        for (int i = 0; i < 2; i++) {
            int idx = tid + i * 256;          // 0..511
            int r = idx >> 2, c4 = idx & 3;
            float4 vv = *(const float4*)&Am[(size_t)(m0 + r) * DIM_ + k0 + c4 * 4];
            As[c4 * 4 + 0][r] = vv.x;
            As[c4 * 4 + 1][r] = vv.y;
            As[c4 * 4 + 2][r] = vv.z;
            As[c4 * 4 + 3][r] = vv.w;
        }
        // B tile: 16 x 128 (direct)
#pragma unroll
        for (int i = 0; i < 2; i++) {
            int idx = tid + i * 256;
            int r = idx >> 5, c4 = idx & 31;
            *(float4*)&Bs[r][c4 * 4] =
                *(const float4*)&Bm[(size_t)(k0 + r) * DIM_ + n0 + c4 * 4];
        }
        __syncthreads();
#pragma unroll
        for (int kk = 0; kk < 16; kk++) {
            float4 a0 = *(float4*)&As[kk][ty * 8];
            float4 a1 = *(float4*)&As[kk][ty * 8 + 4];
            float4 b0 = *(float4*)&Bs[kk][tx * 8];
            float4 b1 = *(float4*)&Bs[kk][tx * 8 + 4];
            float a[8]  = {a0.x, a0.y, a0.z, a0.w, a1.x, a1.y, a1.z, a1.w};
            float bb[8] = {b0.x, b0.y, b0.z, b0.w, b1.x, b1.y, b1.z, b1.w};
#pragma unroll
            for (int i = 0; i < 8; i++)
#pragma unroll
                for (int j = 0; j < 8; j++) acc[i][j] += a[i] * bb[j];
        }
        __syncthreads();
    }
#pragma unroll
    for (int i = 0; i < 8; i++) {
        int m = m0 + ty * 8 + i;
        float* crow = Cm + (size_t)m * DIM_ + n0 + tx * 8;
        float4 o0, o1;
        if (mode == 0) {
            o0 = make_float4(fmaxf(acc[i][0], 0.f), fmaxf(acc[i][1], 0.f),
                             fmaxf(acc[i][2], 0.f), fmaxf(acc[i][3], 0.f));
            o1 = make_float4(fmaxf(acc[i][4], 0.f), fmaxf(acc[i][5], 0.f),
                             fmaxf(acc[i][6], 0.f), fmaxf(acc[i][7], 0.f));
        } else {
            o0 = make_float4(acc[i][0], acc[i][1], acc[i][2], acc[i][3]);
            o1 = make_float4(acc[i][4], acc[i][5], acc[i][6], acc[i][7]);
        }
        *(float4*)&crow[0] = o0;
        *(float4*)&crow[4] = o1;
    }
}

// ---------------- per-token layernorm (GN groups=1) fused with gate mul ----
// Y = (O - mu)/sqrt(var+eps)*gamma + beta;  G = G * Y   (G holds relu(x@wg))
__global__ void gn_kernel(const float* __restrict__ gamma,
                          const float* __restrict__ beta) {
    const int row = blockIdx.x;
    const float* orow = d_O + (size_t)row * DIM_;
    float* grow = d_G + (size_t)row * DIM_;
    const int tid = threadIdx.x;     // 256 threads, 8 cols each

    float v[8];
#pragma unroll
    for (int i = 0; i < 2; i++) {
        float4 t = *(const float4*)&orow[tid * 8 + i * 4];
        v[i * 4 + 0] = t.x; v[i * 4 + 1] = t.y;
        v[i * 4 + 2] = t.z; v[i * 4 + 3] = t.w;
    }

    __shared__ float red[8];
    __shared__ float s_mu, s_inv;

    float lsum = 0.f;
#pragma unroll
    for (int i = 0; i < 8; i++) lsum += v[i];
#pragma unroll
    for (int off = 16; off > 0; off >>= 1) lsum += __shfl_xor_sync(0xffffffffu, lsum, off);
    if ((tid & 31) == 0) red[tid >> 5] = lsum;
    __syncthreads();
    if (tid == 0) {
        float s = 0.f;
#pragma unroll
        for (int w = 0; w < 8; w++) s += red[w];
        s_mu = s * (1.0f / DIM_);
    }
    __syncthreads();
    const float mu = s_mu;

    float lsq = 0.f;
#pragma unroll
    for (int i = 0; i < 8; i++) {
        float d = v[i] - mu;
        lsq += d * d;
    }
#pragma unroll
    for (int off = 16; off > 0; off >>= 1) lsq += __shfl_xor_sync(0xffffffffu, lsq, off);
    __syncthreads();               // red[] reuse safety
    if ((tid & 31) == 0) red[tid >> 5] = lsq;
    __syncthreads();
    if (tid == 0) {
        float s = 0.f;
#pragma unroll
        for (int w = 0; w < 8; w++) s += red[w];
        s_inv = rsqrtf(s * (1.0f / DIM_) + 1e-3f);
    }
    __syncthreads();
    const float inv = s_inv;

#pragma unroll
    for (int i = 0; i < 2; i++) {
        int c0 = tid * 8 + i * 4;
        float4 g4 = *(const float4*)&grow[c0];
        float4 gm = *(const float4*)&gamma[c0];
        float4 bt = *(const float4*)&beta[c0];
        float4 out;
        out.x = g4.x * ((v[i * 4 + 0] - mu) * inv * gm.x + bt.x);
        out.y = g4.y * ((v[i * 4 + 1] - mu) * inv * gm.y + bt.y);
        out.z = g4.z * ((v[i * 4 + 2] - mu) * inv * gm.z + bt.z);
        out.w = g4.w * ((v[i * 4 + 3] - mu) * inv * gm.w + bt.w);
        *(float4*)&grow[c0] = out;
    }
}

// ---------------- launch ----------------
extern "C" void kernel_launch(void* const* d_in, const int* in_sizes, int n_in,
                              void* d_out, int out_size) {
    const float* x     = (const float*)d_in[0];
    const float* k     = (const float*)d_in[1];
    const float* v     = (const float*)d_in[2];
    const float* Wh    = (const float*)d_in[3];
    const float* wg_w  = (const float*)d_in[4];
    const float* wo_w  = (const float*)d_in[5];
    const float* gamma = (const float*)d_in[6];
    const float* beta  = (const float*)d_in[7];
    float* out = (float*)d_out;

    decay_kernel<<<H_, S_>>>();
    qkv_kernel<<<dim3(BSTOT / 64, H_, 3), 256>>>(x, k, v, Wh);
    scores_kernel<<<dim3(S_ / 128, S_ / 64, H_), 256>>>();
    ogemm_kernel<<<dim3(S_ / 64, B_ * H_), 256>>>();
    ff_kernel<<<dim3(DIM_ / 128, BSTOT / 128), 256>>>(x, wg_w, out, 0);   // G = relu(x@wg)
    gn_kernel<<<BSTOT, 256>>>(gamma, beta);                               // G *= LN(O)
    ff_kernel<<<dim3(DIM_ / 128, BSTOT / 128), 256>>>(x, wo_w, out, 1);   // out = G@wo
}